// round 1
// baseline (speedup 1.0000x reference)
#include <cuda_runtime.h>
#include <cfloat>

#define NB 16
#define CC 256
#define KK 204
#define HW 4096

// Scratch (allocation-free): ~57 MB static device globals
__device__ float g_mapping[(size_t)NB * KK * HW];   // (n, k, s)
__device__ int   g_idx[NB * KK];                    // (n, k)
__device__ float g_pooledT[(size_t)NB * KK * CC];   // (n, k, c)  (transposed for coalesced reload)

// ---------------------------------------------------------------------------
// K1: mapping[n,k,s] = sum_c W[k,c] * x[n,c,s]
// Tile 64(k) x 64(s), BK=16, 256 threads, 4x4 microtile.
// ---------------------------------------------------------------------------
__global__ void __launch_bounds__(256) map_gemm(const float* __restrict__ x,
                                                const float* __restrict__ W) {
    __shared__ float Ws[16][68];   // [cc][kr], pad 68 keeps float4 alignment, kills STS conflicts
    __shared__ float Xs[16][64];   // [cc][sc]

    const int s0 = blockIdx.x * 64;
    const int k0 = blockIdx.y * 64;
    const int n  = blockIdx.z;
    const int tid = threadIdx.x;
    const int tx = tid & 15;       // col group
    const int ty = tid >> 4;       // row group

    const float* xb = x + (size_t)n * CC * HW;

    float acc[4][4] = {};

    for (int c0 = 0; c0 < CC; c0 += 16) {
        // Load W tile (coalesced over cc), store transposed
        #pragma unroll
        for (int it = 0; it < 4; it++) {
            int idx = tid + it * 256;
            int kr = idx >> 4, cc = idx & 15;
            int kg = k0 + kr;
            Ws[cc][kr] = (kg < KK) ? W[kg * CC + c0 + cc] : 0.f;
        }
        // Load X tile (coalesced over sc)
        #pragma unroll
        for (int it = 0; it < 4; it++) {
            int idx = tid + it * 256;
            int cc = idx >> 6, sc = idx & 63;
            Xs[cc][sc] = xb[(size_t)(c0 + cc) * HW + s0 + sc];
        }
        __syncthreads();

        #pragma unroll
        for (int cc = 0; cc < 16; cc++) {
            float4 a = *(const float4*)&Ws[cc][ty * 4];
            float4 b = *(const float4*)&Xs[cc][tx * 4];
            float av[4] = {a.x, a.y, a.z, a.w};
            float bv[4] = {b.x, b.y, b.z, b.w};
            #pragma unroll
            for (int i = 0; i < 4; i++)
                #pragma unroll
                for (int j = 0; j < 4; j++)
                    acc[i][j] = fmaf(av[i], bv[j], acc[i][j]);
        }
        __syncthreads();
    }

    #pragma unroll
    for (int i = 0; i < 4; i++) {
        int kg = k0 + ty * 4 + i;
        if (kg < KK) {
            float4 v = make_float4(acc[i][0], acc[i][1], acc[i][2], acc[i][3]);
            *(float4*)&g_mapping[((size_t)n * KK + kg) * HW + s0 + tx * 4] = v;
        }
    }
}

// ---------------------------------------------------------------------------
// K2: idx[n,k] = argmax_s( mapping[n,k,s] + gumbel(U[n,k,s]) )
// First-index tie-break to match jnp.argmax.
// ---------------------------------------------------------------------------
__global__ void __launch_bounds__(256) gumbel_argmax(const float* __restrict__ U) {
    const int row = blockIdx.x;                 // n*KK + k
    const float* m = g_mapping + (size_t)row * HW;
    const float* u = U + (size_t)row * HW;
    const int tid = threadIdx.x;

    float bv = -FLT_MAX;
    int   bi = 0;
    for (int s = tid; s < HW; s += 256) {
        float g = -logf(-logf(u[s] + 1e-20f) + 1e-20f);
        float v = m[s] + g;
        if (v > bv) { bv = v; bi = s; }         // strict > keeps first index within stride
    }

    __shared__ float sv[256];
    __shared__ int   si[256];
    sv[tid] = bv; si[tid] = bi;
    __syncthreads();
    for (int off = 128; off > 0; off >>= 1) {
        if (tid < off) {
            float v2 = sv[tid + off]; int i2 = si[tid + off];
            if (v2 > sv[tid] || (v2 == sv[tid] && i2 < si[tid])) {
                sv[tid] = v2; si[tid] = i2;
            }
        }
        __syncthreads();
    }
    if (tid == 0) g_idx[row] = si[0];
}

// ---------------------------------------------------------------------------
// K3: pooledT[n,k,c] = x[n,c,idx[n,k]]   (st_mask == one-hot in forward pass)
// ---------------------------------------------------------------------------
__global__ void __launch_bounds__(256) pool_gather(const float* __restrict__ x) {
    const int kk = blockIdx.x;
    const int n  = blockIdx.y;
    const int c  = threadIdx.x;
    const int idx = g_idx[n * KK + kk];
    g_pooledT[((size_t)n * KK + kk) * CC + c] = x[((size_t)n * CC + c) * HW + idx];
}

// ---------------------------------------------------------------------------
// K4: attn[:,s] = softmax_k(mapping[:,s]);  out[n,c,s_tile] = pooled @ attn
// s-tile = 64 columns; attn + pooled chunk staged in 104 KB dynamic smem.
// ---------------------------------------------------------------------------
__global__ void __launch_bounds__(256) attn_gemm(float* __restrict__ out) {
    extern __shared__ float sm[];
    float* attn_s = sm;             // [KK][64]
    float* pool_s = sm + KK * 64;   // [KK][64]  (rows = c-chunk of 64)

    const int s0 = blockIdx.x * 64;
    const int n  = blockIdx.y;
    const int tid = threadIdx.x;

    // Phase 1: load mapping tile (coalesced)
    for (int i = tid; i < KK * 64; i += 256) {
        int kk = i >> 6, col = i & 63;
        attn_s[i] = g_mapping[((size_t)n * KK + kk) * HW + s0 + col];
    }
    __syncthreads();

    // Phase 2: column softmax over k (4 threads per column)
    {
        const int col = tid >> 2, p = tid & 3;
        float mx = -FLT_MAX;
        for (int kk = p; kk < KK; kk += 4) mx = fmaxf(mx, attn_s[kk * 64 + col]);
        mx = fmaxf(mx, __shfl_xor_sync(0xFFFFFFFFu, mx, 1));
        mx = fmaxf(mx, __shfl_xor_sync(0xFFFFFFFFu, mx, 2));
        float sum = 0.f;
        for (int kk = p; kk < KK; kk += 4) sum += expf(attn_s[kk * 64 + col] - mx);
        sum += __shfl_xor_sync(0xFFFFFFFFu, sum, 1);
        sum += __shfl_xor_sync(0xFFFFFFFFu, sum, 2);
        float inv = 1.f / sum;
        for (int kk = p; kk < KK; kk += 4)
            attn_s[kk * 64 + col] = expf(attn_s[kk * 64 + col] - mx) * inv;
    }

    const int tx = tid & 15, ty = tid >> 4;

    for (int m0 = 0; m0 < CC; m0 += 64) {
        __syncthreads();            // protect pool_s from previous iteration readers
        for (int i = tid; i < KK * 64; i += 256) {
            int kk = i >> 6, r = i & 63;
            pool_s[i] = g_pooledT[((size_t)n * KK + kk) * CC + m0 + r];
        }
        __syncthreads();

        float acc[4][4] = {};
        #pragma unroll 4
        for (int kk = 0; kk < KK; kk++) {
            float4 a = *(const float4*)&pool_s[kk * 64 + ty * 4];
            float4 b = *(const float4*)&attn_s[kk * 64 + tx * 4];
            float av[4] = {a.x, a.y, a.z, a.w};
            float bv[4] = {b.x, b.y, b.z, b.w};
            #pragma unroll
            for (int i = 0; i < 4; i++)
                #pragma unroll
                for (int j = 0; j < 4; j++)
                    acc[i][j] = fmaf(av[i], bv[j], acc[i][j]);
        }

        #pragma unroll
        for (int i = 0; i < 4; i++) {
            float4 v = make_float4(acc[i][0], acc[i][1], acc[i][2], acc[i][3]);
            *(float4*)&out[((size_t)n * CC + m0 + ty * 4 + i) * HW + s0 + tx * 4] = v;
        }
    }
}

// ---------------------------------------------------------------------------
extern "C" void kernel_launch(void* const* d_in, const int* in_sizes, int n_in,
                              void* d_out, int out_size) {
    const float* x = (const float*)d_in[0];   // (16,256,64,64)
    const float* U = (const float*)d_in[1];   // (16,204,64,64)
    const float* W = (const float*)d_in[2];   // (204,256)
    float* out = (float*)d_out;               // (16,256,64,64)

    const int SMEM_C = 2 * KK * 64 * (int)sizeof(float);  // 104448 B
    cudaFuncSetAttribute(attn_gemm, cudaFuncAttributeMaxDynamicSharedMemorySize, SMEM_C);

    map_gemm<<<dim3(HW / 64, (KK + 63) / 64, NB), 256>>>(x, W);
    gumbel_argmax<<<NB * KK, 256>>>(U);
    pool_gather<<<dim3(KK, NB), 256>>>(x);
    attn_gemm<<<dim3(HW / 64, NB), 256, SMEM_C>>>(out);
}

// round 5
// speedup vs baseline: 1.1923x; 1.1923x over previous
#include <cuda_runtime.h>
#include <cfloat>
#include <cstdint>

#define NB 16
#define CC 256
#define KK 204
#define HW 4096
#define KPAD 208                  // 13 chunks of 16
#define NCH (KPAD / 16)

// Scratch (allocation-free static device globals)
__device__ float g_mapping[(size_t)NB * KK * HW];    // (n, k, s)
__device__ int   g_idx[NB * KK];
__device__ float g_poolA[(size_t)NB * CC * KPAD];    // (n, c, kpad)
__device__ float g_attnT[(size_t)NB * HW * KPAD];    // (n, s, kpad)

__device__ __forceinline__ float tf32r(float v) {
    uint32_t r;
    asm("cvt.rna.tf32.f32 %0, %1;" : "=r"(r) : "f"(v));
    return __uint_as_float(r);
}

__device__ __forceinline__ void mma_tf32(float* c, const uint32_t a[4],
                                         uint32_t b0, uint32_t b1) {
    asm volatile(
        "mma.sync.aligned.m16n8k8.row.col.f32.tf32.tf32.f32 "
        "{%0,%1,%2,%3}, {%4,%5,%6,%7}, {%8,%9}, {%0,%1,%2,%3};"
        : "+f"(c[0]), "+f"(c[1]), "+f"(c[2]), "+f"(c[3])
        : "r"(a[0]), "r"(a[1]), "r"(a[2]), "r"(a[3]), "r"(b0), "r"(b1));
}

// ---------------------------------------------------------------------------
// K1: mapping[n,k,s] = sum_c W[k,c] * x[n,c,s]   (fp32 SIMT, as in R1)
// ---------------------------------------------------------------------------
__global__ void __launch_bounds__(256) map_gemm(const float* __restrict__ x,
                                                const float* __restrict__ W) {
    __shared__ float Ws[16][68];
    __shared__ float Xs[16][64];

    const int s0 = blockIdx.x * 64;
    const int k0 = blockIdx.y * 64;
    const int n  = blockIdx.z;
    const int tid = threadIdx.x;
    const int tx = tid & 15;
    const int ty = tid >> 4;

    const float* xb = x + (size_t)n * CC * HW;
    float acc[4][4] = {};

    for (int c0 = 0; c0 < CC; c0 += 16) {
        #pragma unroll
        for (int it = 0; it < 4; it++) {
            int idx = tid + it * 256;
            int kr = idx >> 4, cc = idx & 15;
            int kg = k0 + kr;
            Ws[cc][kr] = (kg < KK) ? W[kg * CC + c0 + cc] : 0.f;
        }
        #pragma unroll
        for (int it = 0; it < 4; it++) {
            int idx = tid + it * 256;
            int cc = idx >> 6, sc = idx & 63;
            Xs[cc][sc] = xb[(size_t)(c0 + cc) * HW + s0 + sc];
        }
        __syncthreads();
        #pragma unroll
        for (int cc = 0; cc < 16; cc++) {
            float4 a = *(const float4*)&Ws[cc][ty * 4];
            float4 b = *(const float4*)&Xs[cc][tx * 4];
            float av[4] = {a.x, a.y, a.z, a.w};
            float bv[4] = {b.x, b.y, b.z, b.w};
            #pragma unroll
            for (int i = 0; i < 4; i++)
                #pragma unroll
                for (int j = 0; j < 4; j++)
                    acc[i][j] = fmaf(av[i], bv[j], acc[i][j]);
        }
        __syncthreads();
    }

    #pragma unroll
    for (int i = 0; i < 4; i++) {
        int kg = k0 + ty * 4 + i;
        if (kg < KK) {
            float4 v = make_float4(acc[i][0], acc[i][1], acc[i][2], acc[i][3]);
            *(float4*)&g_mapping[((size_t)n * KK + kg) * HW + s0 + tx * 4] = v;
        }
    }
}

// ---------------------------------------------------------------------------
// K2: idx[n,k] = argmax_s( mapping + gumbel(U) )
// ---------------------------------------------------------------------------
__global__ void __launch_bounds__(256) gumbel_argmax(const float* __restrict__ U) {
    const int row = blockIdx.x;
    const float* m = g_mapping + (size_t)row * HW;
    const float* u = U + (size_t)row * HW;
    const int tid = threadIdx.x;

    float bv = -FLT_MAX;
    int   bi = 0;
    for (int s = tid; s < HW; s += 256) {
        float g = -logf(-logf(u[s] + 1e-20f) + 1e-20f);
        float v = m[s] + g;
        if (v > bv) { bv = v; bi = s; }
    }
    __shared__ float sv[256];
    __shared__ int   si[256];
    sv[tid] = bv; si[tid] = bi;
    __syncthreads();
    for (int off = 128; off > 0; off >>= 1) {
        if (tid < off) {
            float v2 = sv[tid + off]; int i2 = si[tid + off];
            if (v2 > sv[tid] || (v2 == sv[tid] && i2 < si[tid])) { sv[tid] = v2; si[tid] = i2; }
        }
        __syncthreads();
    }
    if (tid == 0) g_idx[row] = si[0];
}

// ---------------------------------------------------------------------------
// K3: poolA[n,c,k] = x[n,c,idx[n,k]], zero-padded to KPAD
// ---------------------------------------------------------------------------
__global__ void __launch_bounds__(256) pool_gather(const float* __restrict__ x) {
    const int c = blockIdx.x;
    const int n = blockIdx.y;
    const int k = threadIdx.x;
    if (k < KPAD) {
        float v = 0.f;
        if (k < KK) {
            int idx = g_idx[n * KK + k];
            v = x[((size_t)n * CC + c) * HW + idx];
        }
        g_poolA[((size_t)n * CC + c) * KPAD + k] = v;
    }
}

// ---------------------------------------------------------------------------
// K4a: attnT[n,s,k] = softmax_k(mapping[n,:,s]), zero-padded to KPAD
// ---------------------------------------------------------------------------
__global__ void __launch_bounds__(256) attn_prep() {
    extern __shared__ float sm[];            // [KK][65]
    const int s0 = blockIdx.x * 64;
    const int n  = blockIdx.y;
    const int tid = threadIdx.x;

    for (int i = tid; i < KK * 64; i += 256) {
        int kk = i >> 6, col = i & 63;
        sm[kk * 65 + col] = g_mapping[((size_t)n * KK + kk) * HW + s0 + col];
    }
    __syncthreads();
    {
        const int col = tid >> 2, p = tid & 3;
        float mx = -FLT_MAX;
        for (int kk = p; kk < KK; kk += 4) mx = fmaxf(mx, sm[kk * 65 + col]);
        mx = fmaxf(mx, __shfl_xor_sync(0xFFFFFFFFu, mx, 1));
        mx = fmaxf(mx, __shfl_xor_sync(0xFFFFFFFFu, mx, 2));
        float s = 0.f;
        for (int kk = p; kk < KK; kk += 4) {
            float e = expf(sm[kk * 65 + col] - mx);
            sm[kk * 65 + col] = e;
            s += e;
        }
        s += __shfl_xor_sync(0xFFFFFFFFu, s, 1);
        s += __shfl_xor_sync(0xFFFFFFFFu, s, 2);
        float inv = 1.f / s;
        for (int kk = p; kk < KK; kk += 4)
            sm[kk * 65 + col] *= inv;
    }
    __syncthreads();
    if (tid < KPAD) {
        float* dst = g_attnT + ((size_t)n * HW + s0) * KPAD + tid;
        #pragma unroll 4
        for (int col = 0; col < 64; col++) {
            float v = (tid < KK) ? sm[tid * 65 + col] : 0.f;
            dst[(size_t)col * KPAD] = v;
        }
    }
}

// ---------------------------------------------------------------------------
// K4b: out = poolA @ attnT^T via mma.sync tf32, 3-way split.
// CTA: M=128(c) x N=128(s), 8 warps (4 x m32, 2 x n64), K chunks of 16.
// ---------------------------------------------------------------------------
#define LDK 17                               // smem row stride (floats)
#define CHF (128 * LDK)                      // floats per operand plane

__global__ void __launch_bounds__(256) attn_gemm_mma(float* __restrict__ out) {
    extern __shared__ float sm[];
    // layout per buffer: Ah, Al, Bh, Bl each CHF floats
    const int s0 = blockIdx.x * 128;
    const int c0 = blockIdx.y * 128;
    const int n  = blockIdx.z;
    const int tid  = threadIdx.x;
    const int lane = tid & 31;
    const int wid  = tid >> 5;
    const int wm   = wid & 3;                // warp row block (32 rows)
    const int wn   = wid >> 2;               // warp col block (64 cols)
    const int g    = lane >> 2;              // groupID
    const int t4   = lane & 3;

    const float* Ag = g_poolA + ((size_t)n * CC + c0) * KPAD;
    const float* Bg = g_attnT + ((size_t)n * HW + s0) * KPAD;

    float acc[2][8][4];
    #pragma unroll
    for (int f = 0; f < 2; f++)
        #pragma unroll
        for (int nb = 0; nb < 8; nb++)
            #pragma unroll
            for (int j = 0; j < 4; j++) acc[f][nb][j] = 0.f;

    const int lr = tid >> 2;                 // 0..63  (row group for loads)
    const int lc = (tid & 3) * 4;            // 0,4,8,12

    // ---- load one K16 chunk into buffer b ----
    auto load_chunk = [&](int ch, int b) {
        float* Ah = sm + b * 4 * CHF;
        float* Al = Ah + CHF;
        float* Bh = Al + CHF;
        float* Bl = Bh + CHF;
        #pragma unroll
        for (int it = 0; it < 2; it++) {
            int r = lr + it * 64;
            float4 va = *(const float4*)(Ag + (size_t)r * KPAD + ch * 16 + lc);
            float4 vb = *(const float4*)(Bg + (size_t)r * KPAD + ch * 16 + lc);
            float h;
            int base = r * LDK + lc;
            h = tf32r(va.x); Ah[base + 0] = h; Al[base + 0] = tf32r(va.x - h);
            h = tf32r(va.y); Ah[base + 1] = h; Al[base + 1] = tf32r(va.y - h);
            h = tf32r(va.z); Ah[base + 2] = h; Al[base + 2] = tf32r(va.z - h);
            h = tf32r(va.w); Ah[base + 3] = h; Al[base + 3] = tf32r(va.w - h);
            h = tf32r(vb.x); Bh[base + 0] = h; Bl[base + 0] = tf32r(vb.x - h);
            h = tf32r(vb.y); Bh[base + 1] = h; Bl[base + 1] = tf32r(vb.y - h);
            h = tf32r(vb.z); Bh[base + 2] = h; Bl[base + 2] = tf32r(vb.z - h);
            h = tf32r(vb.w); Bh[base + 3] = h; Bl[base + 3] = tf32r(vb.w - h);
        }
    };

    load_chunk(0, 0);
    __syncthreads();

    for (int ch = 0; ch < NCH; ch++) {
        if (ch + 1 < NCH) load_chunk(ch + 1, (ch + 1) & 1);

        const float* Ah = sm + (ch & 1) * 4 * CHF;
        const float* Al = Ah + CHF;
        const float* Bh = Al + CHF;
        const float* Bl = Bh + CHF;

        #pragma unroll
        for (int k8 = 0; k8 < 2; k8++) {
            const int kc = k8 * 8 + t4;
            uint32_t ah[2][4], al[2][4];
            #pragma unroll
            for (int f = 0; f < 2; f++) {
                int row = wm * 32 + f * 16 + g;
                ah[f][0] = __float_as_uint(Ah[row * LDK + kc]);
                ah[f][1] = __float_as_uint(Ah[(row + 8) * LDK + kc]);
                ah[f][2] = __float_as_uint(Ah[row * LDK + kc + 4]);
                ah[f][3] = __float_as_uint(Ah[(row + 8) * LDK + kc + 4]);
                al[f][0] = __float_as_uint(Al[row * LDK + kc]);
                al[f][1] = __float_as_uint(Al[(row + 8) * LDK + kc]);
                al[f][2] = __float_as_uint(Al[row * LDK + kc + 4]);
                al[f][3] = __float_as_uint(Al[(row + 8) * LDK + kc + 4]);
            }
            #pragma unroll
            for (int nb = 0; nb < 8; nb++) {
                int bn = wn * 64 + nb * 8 + g;
                uint32_t bh0 = __float_as_uint(Bh[bn * LDK + kc]);
                uint32_t bh1 = __float_as_uint(Bh[bn * LDK + kc + 4]);
                uint32_t bl0 = __float_as_uint(Bl[bn * LDK + kc]);
                uint32_t bl1 = __float_as_uint(Bl[bn * LDK + kc + 4]);
                #pragma unroll
                for (int f = 0; f < 2; f++) {
                    mma_tf32(acc[f][nb], ah[f], bh0, bh1);
                    mma_tf32(acc[f][nb], al[f], bh0, bh1);
                    mma_tf32(acc[f][nb], ah[f], bl0, bl1);
                }
            }
        }
        __syncthreads();
    }

    // Epilogue: c0=C[g][2t4], c1=C[g][2t4+1], c2=C[g+8][2t4], c3=C[g+8][2t4+1]
    #pragma unroll
    for (int f = 0; f < 2; f++) {
        #pragma unroll
        for (int nb = 0; nb < 8; nb++) {
            int row = c0 + wm * 32 + f * 16 + g;
            int col = s0 + wn * 64 + nb * 8 + 2 * t4;
            float* p0 = out + ((size_t)n * CC + row) * HW + col;
            float* p1 = out + ((size_t)n * CC + row + 8) * HW + col;
            p0[0] = acc[f][nb][0]; p0[1] = acc[f][nb][1];
            p1[0] = acc[f][nb][2]; p1[1] = acc[f][nb][3];
        }
    }
}

// ---------------------------------------------------------------------------
extern "C" void kernel_launch(void* const* d_in, const int* in_sizes, int n_in,
                              void* d_out, int out_size) {
    const float* x = (const float*)d_in[0];   // (16,256,64,64)
    const float* U = (const float*)d_in[1];   // (16,204,64,64)
    const float* W = (const float*)d_in[2];   // (204,256)
    float* out = (float*)d_out;               // (16,256,64,64)

    const int SMEM_PREP = KK * 65 * (int)sizeof(float);          // 53040
    const int SMEM_MMA  = 2 * 4 * CHF * (int)sizeof(float);      // 69632
    cudaFuncSetAttribute(attn_prep, cudaFuncAttributeMaxDynamicSharedMemorySize, SMEM_PREP);
    cudaFuncSetAttribute(attn_gemm_mma, cudaFuncAttributeMaxDynamicSharedMemorySize, SMEM_MMA);

    map_gemm<<<dim3(HW / 64, (KK + 63) / 64, NB), 256>>>(x, W);
    gumbel_argmax<<<NB * KK, 256>>>(U);
    pool_gather<<<dim3(CC, NB), 256>>>(x);
    attn_prep<<<dim3(HW / 64, NB), 256, SMEM_PREP>>>();
    attn_gemm_mma<<<dim3(HW / 128, CC / 128, NB), 256, SMEM_MMA>>>(out);
}